// round 2
// baseline (speedup 1.0000x reference)
#include <cuda_runtime.h>
#include <math.h>

#define BATCH 64
#define SEQ   1024
#define CDIM  128
#define NEGV  -1e32f

// Scratch for Q, K, V projections (3 x 32 MB). Static device globals (no alloc).
__device__ float g_Q[BATCH * SEQ * CDIM];
__device__ float g_K[BATCH * SEQ * CDIM];
__device__ float g_V[BATCH * SEQ * CDIM];

static __device__ __forceinline__ float4 f4_scale(float4 a, float s) {
    return make_float4(a.x * s, a.y * s, a.z * s, a.w * s);
}
static __device__ __forceinline__ float4 f4_fma(float p, float4 v, float4 acc) {
    acc.x = fmaf(p, v.x, acc.x);
    acc.y = fmaf(p, v.y, acc.y);
    acc.z = fmaf(p, v.z, acc.z);
    acc.w = fmaf(p, v.w, acc.w);
    return acc;
}
static __device__ __forceinline__ float f4_dot_acc(float4 a, float4 b, float acc) {
    acc = fmaf(a.x, b.x, acc);
    acc = fmaf(a.y, b.y, acc);
    acc = fmaf(a.z, b.z, acc);
    acc = fmaf(a.w, b.w, acc);
    return acc;
}

// ============================================================================
// Kernel 1: fused QKV projection.
// out[n][c] = sum_k x[n][k] * W[c][k] + b[c]  for W in {q_w, k_w, v_w}.
// One block = 64 rows of x. X tile and W matrix live in smem (float4, padded
// stride 33 to kill bank conflicts). Thread (ty,tx): rows ty+16i, cols tx+16j.
// ============================================================================
#define QKV_SMEM ((64 + 128) * 33 * 16)

__global__ __launch_bounds__(256, 2)
void qkv_kernel(const float* __restrict__ x,
                const float* __restrict__ qw, const float* __restrict__ qb,
                const float* __restrict__ kw, const float* __restrict__ kb,
                const float* __restrict__ vw, const float* __restrict__ vb)
{
    extern __shared__ float4 smem[];
    float4* sX = smem;             // 64 rows x 33 float4
    float4* sW = smem + 64 * 33;   // 128 rows x 33 float4

    const int tid = threadIdx.x;
    const int tx = tid & 15;
    const int ty = tid >> 4;
    const int row0 = blockIdx.x * 64;

    // Load X tile (64 x 128 floats = 64 x 32 float4)
    const float4* xg = (const float4*)(x + (size_t)row0 * CDIM);
    for (int idx = tid; idx < 64 * 32; idx += 256) {
        int r = idx >> 5, k4 = idx & 31;
        sX[r * 33 + k4] = xg[r * 32 + k4];
    }

    const float* Wt[3] = {qw, kw, vw};
    const float* Bt[3] = {qb, kb, vb};
    float* Ot[3] = {g_Q, g_K, g_V};

    for (int w = 0; w < 3; w++) {
        __syncthreads();  // previous compute done before overwriting sW
        const float4* wg = (const float4*)Wt[w];
        for (int idx = tid; idx < 128 * 32; idx += 256) {
            int r = idx >> 5, k4 = idx & 31;
            sW[r * 33 + k4] = wg[r * 32 + k4];
        }
        __syncthreads();  // sX (first iter) and sW visible

        float bias[8];
        #pragma unroll
        for (int j = 0; j < 8; j++) bias[j] = Bt[w][tx + 16 * j];

        float acc[4][8];
        #pragma unroll
        for (int i = 0; i < 4; i++)
            #pragma unroll
            for (int j = 0; j < 8; j++) acc[i][j] = 0.f;

        #pragma unroll 8
        for (int k4 = 0; k4 < 32; k4++) {
            float4 a[4], bv[8];
            #pragma unroll
            for (int i = 0; i < 4; i++) a[i] = sX[(ty + 16 * i) * 33 + k4];
            #pragma unroll
            for (int j = 0; j < 8; j++) bv[j] = sW[(tx + 16 * j) * 33 + k4];
            #pragma unroll
            for (int i = 0; i < 4; i++)
                #pragma unroll
                for (int j = 0; j < 8; j++)
                    acc[i][j] = f4_dot_acc(a[i], bv[j], acc[i][j]);
        }

        float* O = Ot[w];
        #pragma unroll
        for (int i = 0; i < 4; i++) {
            int r = row0 + ty + 16 * i;
            #pragma unroll
            for (int j = 0; j < 8; j++)
                O[(size_t)r * CDIM + tx + 16 * j] = acc[i][j] + bias[j];
        }
    }
}

// ============================================================================
// Kernel 2: flash-style masked attention.
// Block = (batch b, 64-row q-tile). Online softmax over K tiles of 64 rows,
// skipping tiles entirely past valid_len. Rows >= valid_len output exact 0.
// Thread (ty,tx): S rows ty+16i, S cols tx+16j; O rows ty+16i, O d4 = tx+16j4.
// smem: sQ | (sK aliased with sP) | sV  -> ~99 KB, 2 CTAs/SM.
// ============================================================================
#define ATT_SMEM (3 * 64 * 33 * 16)

__global__ __launch_bounds__(256, 2)
void attn_kernel(const int* __restrict__ valid_lens, float* __restrict__ out)
{
    extern __shared__ float4 smem[];
    float4* sQ  = smem;                 // 64 x 33 f4
    float4* sKP = smem + 64 * 33;       // union: K tile / P tile
    float4* sV  = smem + 2 * 64 * 33;   // 64 x 33 f4
    float*  sP  = (float*)sKP;          // 64 x 65 floats (16.6 KB <= 33 KB)

    const int tid = threadIdx.x;
    const int tx = tid & 15;
    const int ty = tid >> 4;
    const int b  = blockIdx.y;
    const int qt = blockIdx.x;
    const int row0 = qt * 64;
    const int vl = valid_lens[b];

    float* og = out + (size_t)(b * SEQ + row0) * CDIM;

    if (row0 >= vl) {
        // whole tile is masked rows -> exact zeros
        float4* o4 = (float4*)og;
        float4 z = make_float4(0.f, 0.f, 0.f, 0.f);
        for (int idx = tid; idx < 64 * 32; idx += 256) o4[idx] = z;
        return;
    }

    // Load Q tile
    const float4* Qg = (const float4*)(g_Q + (size_t)(b * SEQ + row0) * CDIM);
    for (int idx = tid; idx < 64 * 32; idx += 256) {
        int r = idx >> 5, k4 = idx & 31;
        sQ[r * 33 + k4] = Qg[r * 32 + k4];
    }

    float m[4], l[4];
    float4 o[4][2];
    #pragma unroll
    for (int i = 0; i < 4; i++) {
        m[i] = -INFINITY;
        l[i] = 0.f;
        o[i][0] = make_float4(0.f, 0.f, 0.f, 0.f);
        o[i][1] = make_float4(0.f, 0.f, 0.f, 0.f);
    }

    const int nkt = (vl + 63) >> 6;  // only tiles with a valid column
    for (int kt = 0; kt < nkt; kt++) {
        const float4* Kg = (const float4*)(g_K + (size_t)(b * SEQ + kt * 64) * CDIM);
        const float4* Vg = (const float4*)(g_V + (size_t)(b * SEQ + kt * 64) * CDIM);
        __syncthreads();  // previous PV (reads sP,sV) done; sQ visible (kt=0)
        for (int idx = tid; idx < 64 * 32; idx += 256) {
            int r = idx >> 5, k4 = idx & 31;
            sKP[r * 33 + k4] = Kg[r * 32 + k4];
            sV[r * 33 + k4]  = Vg[r * 32 + k4];
        }
        __syncthreads();  // K, V visible

        // S = Q K^T (4x4 per thread)
        float s[4][4];
        #pragma unroll
        for (int i = 0; i < 4; i++)
            #pragma unroll
            for (int j = 0; j < 4; j++) s[i][j] = 0.f;

        #pragma unroll 8
        for (int k4 = 0; k4 < 32; k4++) {
            float4 a[4], bb[4];
            #pragma unroll
            for (int i = 0; i < 4; i++) a[i] = sQ[(ty + 16 * i) * 33 + k4];
            #pragma unroll
            for (int j = 0; j < 4; j++) bb[j] = sKP[(tx + 16 * j) * 33 + k4];
            #pragma unroll
            for (int i = 0; i < 4; i++)
                #pragma unroll
                for (int j = 0; j < 4; j++)
                    s[i][j] = f4_dot_acc(a[i], bb[j], s[i][j]);
        }

        // mask columns >= vl
        const int cbase = kt * 64;
        #pragma unroll
        for (int j = 0; j < 4; j++) {
            int c = cbase + tx + 16 * j;
            if (c >= vl) {
                #pragma unroll
                for (int i = 0; i < 4; i++) s[i][j] = NEGV;
            }
        }

        // online softmax update
        float mt[4], mn[4], scale[4], rs[4];
        #pragma unroll
        for (int i = 0; i < 4; i++) {
            mt[i] = fmaxf(fmaxf(s[i][0], s[i][1]), fmaxf(s[i][2], s[i][3]));
            #pragma unroll
            for (int off = 1; off < 16; off <<= 1)
                mt[i] = fmaxf(mt[i], __shfl_xor_sync(0xffffffffu, mt[i], off));
            mn[i] = fmaxf(m[i], mt[i]);
            scale[i] = __expf(m[i] - mn[i]);   // first tile: exp(-inf)=0
            m[i] = mn[i];
        }
        #pragma unroll
        for (int i = 0; i < 4; i++) {
            rs[i] = 0.f;
            #pragma unroll
            for (int j = 0; j < 4; j++) {
                s[i][j] = __expf(s[i][j] - mn[i]);   // masked -> exp(-1e32)=0
                rs[i] += s[i][j];
            }
            #pragma unroll
            for (int off = 1; off < 16; off <<= 1)
                rs[i] += __shfl_xor_sync(0xffffffffu, rs[i], off);
            l[i] = l[i] * scale[i] + rs[i];
            o[i][0] = f4_scale(o[i][0], scale[i]);
            o[i][1] = f4_scale(o[i][1], scale[i]);
        }

        __syncthreads();  // everyone done reading sKP as K
        #pragma unroll
        for (int i = 0; i < 4; i++)
            #pragma unroll
            for (int j = 0; j < 4; j++)
                sP[(ty + 16 * i) * 65 + tx + 16 * j] = s[i][j];
        __syncthreads();  // P visible

        // O += P * V
        #pragma unroll 4
        for (int c = 0; c < 64; c++) {
            float p0 = sP[(ty     ) * 65 + c];
            float p1 = sP[(ty + 16) * 65 + c];
            float p2 = sP[(ty + 32) * 65 + c];
            float p3 = sP[(ty + 48) * 65 + c];
            float4 v0 = sV[c * 33 + tx];
            float4 v1 = sV[c * 33 + tx + 16];
            o[0][0] = f4_fma(p0, v0, o[0][0]);  o[0][1] = f4_fma(p0, v1, o[0][1]);
            o[1][0] = f4_fma(p1, v0, o[1][0]);  o[1][1] = f4_fma(p1, v1, o[1][1]);
            o[2][0] = f4_fma(p2, v0, o[2][0]);  o[2][1] = f4_fma(p2, v1, o[2][1]);
            o[3][0] = f4_fma(p3, v0, o[3][0]);  o[3][1] = f4_fma(p3, v1, o[3][1]);
        }
    }

    // epilogue: normalize; zero rows >= vl (reference zeroes masked rows)
    float4* og4 = (float4*)og;
    #pragma unroll
    for (int i = 0; i < 4; i++) {
        int r = ty + 16 * i;
        float inv = (row0 + r < vl) ? (1.f / l[i]) : 0.f;
        og4[r * 32 + tx     ] = f4_scale(o[i][0], inv);
        og4[r * 32 + tx + 16] = f4_scale(o[i][1], inv);
    }
}

// ============================================================================
// Launcher
// ============================================================================
extern "C" void kernel_launch(void* const* d_in, const int* in_sizes, int n_in,
                              void* d_out, int out_size)
{
    const float* x  = (const float*)d_in[0];
    const int*   vl = (const int*)  d_in[1];
    const float* qw = (const float*)d_in[2];
    const float* qb = (const float*)d_in[3];
    const float* kw = (const float*)d_in[4];
    const float* kb = (const float*)d_in[5];
    const float* vw = (const float*)d_in[6];
    const float* vb = (const float*)d_in[7];
    float* out = (float*)d_out;

    cudaFuncSetAttribute(qkv_kernel,  cudaFuncAttributeMaxDynamicSharedMemorySize, QKV_SMEM);
    cudaFuncSetAttribute(attn_kernel, cudaFuncAttributeMaxDynamicSharedMemorySize, ATT_SMEM);

    qkv_kernel<<<(BATCH * SEQ) / 64, 256, QKV_SMEM>>>(x, qw, qb, kw, kb, vw, vb);

    dim3 grid(SEQ / 64, BATCH);
    attn_kernel<<<grid, 256, ATT_SMEM>>>(vl, out);
}

// round 4
// speedup vs baseline: 1.9690x; 1.9690x over previous
#include <cuda_runtime.h>
#include <cuda_bf16.h>
#include <math.h>
#include <stdint.h>

#define BATCH 64
#define SEQ   1024
#define CDIM  128
#define M0    40.0f

// bf16 hi/lo scratch (zero-initialized device globals):
// Q,K row-major [b*n][c]; V transposed [b][c][n]
__device__ __align__(16) unsigned short g_Qh[BATCH * SEQ * CDIM];
__device__ __align__(16) unsigned short g_Ql[BATCH * SEQ * CDIM];
__device__ __align__(16) unsigned short g_Kh[BATCH * SEQ * CDIM];
__device__ __align__(16) unsigned short g_Kl[BATCH * SEQ * CDIM];
__device__ __align__(16) unsigned short g_Vth[BATCH * CDIM * SEQ];
__device__ __align__(16) unsigned short g_Vtl[BATCH * CDIM * SEQ];

// ---------------- helpers ----------------
static __device__ __forceinline__ uint32_t smem_u32(const void* p) {
    uint32_t a;
    asm("{ .reg .u64 t; cvta.to.shared.u64 t, %1; cvt.u32.u64 %0, t; }" : "=r"(a) : "l"(p));
    return a;
}
static __device__ __forceinline__ void ldmx4(uint32_t a, uint32_t* r) {
    asm volatile("ldmatrix.sync.aligned.m8n8.x4.shared.b16 {%0,%1,%2,%3}, [%4];"
                 : "=r"(r[0]), "=r"(r[1]), "=r"(r[2]), "=r"(r[3]) : "r"(a));
}
static __device__ __forceinline__ void ldmx2(uint32_t a, uint32_t* r) {
    asm volatile("ldmatrix.sync.aligned.m8n8.x2.shared.b16 {%0,%1}, [%2];"
                 : "=r"(r[0]), "=r"(r[1]) : "r"(a));
}
static __device__ __forceinline__ void mma16816(float* d, const uint32_t* a, const uint32_t* b) {
    asm volatile("mma.sync.aligned.m16n8k16.row.col.f32.bf16.bf16.f32 "
                 "{%0,%1,%2,%3}, {%4,%5,%6,%7}, {%8,%9}, {%0,%1,%2,%3};"
                 : "+f"(d[0]), "+f"(d[1]), "+f"(d[2]), "+f"(d[3])
                 : "r"(a[0]), "r"(a[1]), "r"(a[2]), "r"(a[3]), "r"(b[0]), "r"(b[1]));
}
// pack two floats -> bf16x2 (lo in low half, hi in high half)
static __device__ __forceinline__ uint32_t cvt2(float lo, float hi) {
    uint32_t r;
    asm("cvt.rn.bf16x2.f32 %0, %1, %2;" : "=r"(r) : "f"(hi), "f"(lo));
    return r;
}

#define TSTRIDE 272                  // bytes per smem tile row (bank-quartet safe)
#define TILE_B  (128 * TSTRIDE)      // 34816
#define OFF_QH  0
#define OFF_QL  (1 * TILE_B)
#define OFF_KH  (2 * TILE_B)
#define OFF_KL  (3 * TILE_B)
#define OFF_VH  (4 * TILE_B)
#define OFF_VL  (5 * TILE_B)
#define ATT_SMEM (6 * TILE_B)        // 208896 B

// async-copy a 128-row x 128-bf16 tile (256B/row) into 272B-stride smem
static __device__ __forceinline__ void load_tile(uint32_t sdst, const unsigned short* g,
                                                 int rstride, int tid) {
    #pragma unroll
    for (int i = 0; i < 8; i++) {
        int idx = tid + (i << 8);            // 2048 16B chunks
        int r = idx >> 4, c = idx & 15;
        uint32_t d = sdst + (uint32_t)r * TSTRIDE + (uint32_t)c * 16;
        const void* gp = (const void*)(g + (size_t)r * rstride + (c << 3));
        asm volatile("cp.async.cg.shared.global [%0], [%1], 16;" :: "r"(d), "l"(gp));
    }
}

// ============================================================================
// Kernel 1: QKV projection -> bf16 hi/lo (Q,K row-major; V transposed).
// Skips 64-row blocks that are entirely masked.
// ============================================================================
#define QKV_SMEM ((64 + 128) * 33 * 16)

__global__ __launch_bounds__(256, 2)
void qkv_kernel(const float* __restrict__ x, const int* __restrict__ vls,
                const float* __restrict__ qw, const float* __restrict__ qb,
                const float* __restrict__ kw, const float* __restrict__ kb,
                const float* __restrict__ vw, const float* __restrict__ vb)
{
    extern __shared__ float4 smem[];
    float4* sX = smem;
    float4* sW = smem + 64 * 33;
    const int tid = threadIdx.x, tx = tid & 15, ty = tid >> 4;
    const int row0 = blockIdx.x * 64;
    const int b = row0 >> 10, n0 = row0 & 1023;
    if (n0 >= vls[b]) return;

    const float4* xg = (const float4*)(x + (size_t)row0 * CDIM);
    for (int idx = tid; idx < 64 * 32; idx += 256) {
        int r = idx >> 5, k4 = idx & 31;
        sX[r * 33 + k4] = xg[r * 32 + k4];
    }
    const float* Wt[3] = {qw, kw, vw};
    const float* Bt[3] = {qb, kb, vb};

    for (int w = 0; w < 3; w++) {
        __syncthreads();
        const float4* wg = (const float4*)Wt[w];
        for (int idx = tid; idx < 128 * 32; idx += 256) {
            int r = idx >> 5, k4 = idx & 31;
            sW[r * 33 + k4] = wg[r * 32 + k4];
        }
        __syncthreads();

        float bias[8];
        #pragma unroll
        for (int j = 0; j < 8; j++) bias[j] = Bt[w][tx + 16 * j];
        float acc[4][8];
        #pragma unroll
        for (int i = 0; i < 4; i++)
            #pragma unroll
            for (int j = 0; j < 8; j++) acc[i][j] = 0.f;

        #pragma unroll 8
        for (int k4 = 0; k4 < 32; k4++) {
            float4 a[4], bv[8];
            #pragma unroll
            for (int i = 0; i < 4; i++) a[i] = sX[(ty + 16 * i) * 33 + k4];
            #pragma unroll
            for (int j = 0; j < 8; j++) bv[j] = sW[(tx + 16 * j) * 33 + k4];
            #pragma unroll
            for (int i = 0; i < 4; i++)
                #pragma unroll
                for (int j = 0; j < 8; j++) {
                    acc[i][j] = fmaf(a[i].x, bv[j].x, acc[i][j]);
                    acc[i][j] = fmaf(a[i].y, bv[j].y, acc[i][j]);
                    acc[i][j] = fmaf(a[i].z, bv[j].z, acc[i][j]);
                    acc[i][j] = fmaf(a[i].w, bv[j].w, acc[i][j]);
                }
        }

        if (w < 2) {
            unsigned short* Oh = (w == 0) ? g_Qh : g_Kh;
            unsigned short* Ol = (w == 0) ? g_Ql : g_Kl;
            #pragma unroll
            for (int i = 0; i < 4; i++) {
                size_t r = (size_t)(row0 + ty + 16 * i) * CDIM;
                #pragma unroll
                for (int j = 0; j < 8; j++) {
                    float v = acc[i][j] + bias[j];
                    __nv_bfloat16 h = __float2bfloat16(v);
                    Oh[r + tx + 16 * j] = __bfloat16_as_ushort(h);
                    Ol[r + tx + 16 * j] = __bfloat16_as_ushort(__float2bfloat16(v - __bfloat162float(h)));
                }
            }
        } else {
            __syncthreads();  // done reading sX/sW; reuse smem for transpose
            unsigned short* sTh = (unsigned short*)smem;   // [128][66]
            unsigned short* sTl = sTh + 128 * 66;
            #pragma unroll
            for (int i = 0; i < 4; i++) {
                int nl = ty + 16 * i;
                #pragma unroll
                for (int j = 0; j < 8; j++) {
                    int c = tx + 16 * j;
                    float v = acc[i][j] + bias[j];
                    __nv_bfloat16 h = __float2bfloat16(v);
                    sTh[c * 66 + nl] = __bfloat16_as_ushort(h);
                    sTl[c * 66 + nl] = __bfloat16_as_ushort(__float2bfloat16(v - __bfloat162float(h)));
                }
            }
            __syncthreads();
            int wid = tid >> 5, lane = tid & 31;
            size_t obase = (size_t)b * CDIM * SEQ + n0;
            #pragma unroll
            for (int rr = 0; rr < 16; rr++) {
                int c = rr * 8 + wid;
                uint32_t hv = *(const uint32_t*)(sTh + c * 66 + lane * 2);
                uint32_t lv = *(const uint32_t*)(sTl + c * 66 + lane * 2);
                ((uint32_t*)(g_Vth + obase + (size_t)c * SEQ))[lane] = hv;
                ((uint32_t*)(g_Vtl + obase + (size_t)c * SEQ))[lane] = lv;
            }
        }
    }
}

// ============================================================================
// Kernel 2: mma.sync flash attention, 2-term bf16 split, fixed-M0 softmax.
// CTA = 128 q-rows x batch. 8 warps; warp w owns q-rows 16w..16w+15.
// O accumulates in registers across K-tiles; one normalize at end.
// ============================================================================
__global__ __launch_bounds__(256)
void attn_mma(const int* __restrict__ vls, float* __restrict__ out)
{
    extern __shared__ __align__(16) char sm[];
    const uint32_t sb = smem_u32(sm);
    const int tid = threadIdx.x, wid = tid >> 5, lane = tid & 31;
    const int b = blockIdx.y, row0 = blockIdx.x * 128;
    const int vl = vls[b];
    float* og = out + ((size_t)b * SEQ + row0) * CDIM;

    if (row0 >= vl) {                       // fully masked -> exact zeros
        float4 z = make_float4(0.f, 0.f, 0.f, 0.f);
        float4* o4 = (float4*)og;
        for (int i = tid; i < 128 * 32; i += 256) o4[i] = z;
        return;
    }

    // per-thread ldmatrix address offsets
    const uint32_t qrow = (uint32_t)(wid * 16 + (lane & 15)) * TSTRIDE + ((lane >> 4) & 1) * 16;
    const uint32_t brow = (uint32_t)(lane & 7) * TSTRIDE + ((lane >> 3) & 1) * 16;

    // issue Q loads now; first wait_all inside loop covers them
    load_tile(sb + OFF_QH, g_Qh + ((size_t)b * SEQ + row0) * CDIM, CDIM, tid);
    load_tile(sb + OFF_QL, g_Ql + ((size_t)b * SEQ + row0) * CDIM, CDIM, tid);

    const int r0l = wid * 16 + (lane >> 2);  // local row of accum row0
    const int r0g = row0 + r0l, r1g = r0g + 8;
    const bool v0 = r0g < vl, v1 = r1g < vl;

    float oacc[16][4];
    #pragma unroll
    for (int n = 0; n < 16; n++)
        #pragma unroll
        for (int q = 0; q < 4; q++) oacc[n][q] = 0.f;
    float lsum0 = 0.f, lsum1 = 0.f;

    const int nkt = (vl + 127) >> 7;
    for (int kt = 0; kt < nkt; kt++) {
        __syncthreads();                     // prior iter's smem reads done
        size_t kb = ((size_t)b * SEQ + (size_t)kt * 128) * CDIM;
        size_t vb0 = (size_t)b * CDIM * SEQ + (size_t)kt * 128;
        load_tile(sb + OFF_KH, g_Kh + kb, CDIM, tid);
        load_tile(sb + OFF_KL, g_Kl + kb, CDIM, tid);
        load_tile(sb + OFF_VH, g_Vth + vb0, SEQ, tid);
        load_tile(sb + OFF_VL, g_Vtl + vb0, SEQ, tid);
        asm volatile("cp.async.wait_all;" ::: "memory");
        __syncthreads();

        // ---- S = Q K^T  (3 split terms, fp32 accum) ----
        float sacc[16][4];
        #pragma unroll
        for (int n = 0; n < 16; n++)
            #pragma unroll
            for (int q = 0; q < 4; q++) sacc[n][q] = 0.f;

        #pragma unroll
        for (int ks = 0; ks < 8; ks++) {
            uint32_t qh[4], ql[4];
            ldmx4(sb + OFF_QH + qrow + ks * 32, qh);
            ldmx4(sb + OFF_QL + qrow + ks * 32, ql);
            #pragma unroll
            for (int n = 0; n < 16; n++) {
                uint32_t bh[2], bl[2];
                uint32_t off = brow + (uint32_t)n * (8 * TSTRIDE) + ks * 32;
                ldmx2(sb + OFF_KH + off, bh);
                ldmx2(sb + OFF_KL + off, bl);
                mma16816(sacc[n], qh, bh);
                mma16816(sacc[n], ql, bh);
                mma16816(sacc[n], qh, bl);
            }
        }

        // ---- softmax: e = exp(clamp(s - M0)) with row/col masks ----
        #pragma unroll
        for (int n = 0; n < 16; n++) {
            int c0 = kt * 128 + n * 8 + (lane & 3) * 2;
            float e0 = (v0 && c0 < vl)     ? __expf(fminf(fmaxf(sacc[n][0] - M0, -80.f), 80.f)) : 0.f;
            float e1 = (v0 && c0 + 1 < vl) ? __expf(fminf(fmaxf(sacc[n][1] - M0, -80.f), 80.f)) : 0.f;
            float e2 = (v1 && c0 < vl)     ? __expf(fminf(fmaxf(sacc[n][2] - M0, -80.f), 80.f)) : 0.f;
            float e3 = (v1 && c0 + 1 < vl) ? __expf(fminf(fmaxf(sacc[n][3] - M0, -80.f), 80.f)) : 0.f;
            lsum0 += e0 + e1;
            lsum1 += e2 + e3;
            sacc[n][0] = e0; sacc[n][1] = e1; sacc[n][2] = e2; sacc[n][3] = e3;
        }

        // ---- O += P V  (P from accum fragments, 3 split terms) ----
        #pragma unroll
        for (int ks = 0; ks < 8; ks++) {
            const float* t0 = sacc[2 * ks];
            const float* t1 = sacc[2 * ks + 1];
            uint32_t ph[4], pl[4];
            ph[0] = cvt2(t0[0], t0[1]);
            ph[1] = cvt2(t0[2], t0[3]);
            ph[2] = cvt2(t1[0], t1[1]);
            ph[3] = cvt2(t1[2], t1[3]);
            pl[0] = cvt2(t0[0] - __uint_as_float(ph[0] << 16), t0[1] - __uint_as_float(ph[0] & 0xffff0000u));
            pl[1] = cvt2(t0[2] - __uint_as_float(ph[1] << 16), t0[3] - __uint_as_float(ph[1] & 0xffff0000u));
            pl[2] = cvt2(t1[0] - __uint_as_float(ph[2] << 16), t1[1] - __uint_as_float(ph[2] & 0xffff0000u));
            pl[3] = cvt2(t1[2] - __uint_as_float(ph[3] << 16), t1[3] - __uint_as_float(ph[3] & 0xffff0000u));
            #pragma unroll
            for (int n = 0; n < 16; n++) {
                uint32_t bh[2], bl[2];
                uint32_t off = brow + (uint32_t)n * (8 * TSTRIDE) + ks * 32;
                ldmx2(sb + OFF_VH + off, bh);
                ldmx2(sb + OFF_VL + off, bl);
                mma16816(oacc[n], ph, bh);
                mma16816(oacc[n], pl, bh);
                mma16816(oacc[n], ph, bl);
            }
        }
    }

    // ---- epilogue: reduce l over quad, normalize, store ----
    lsum0 += __shfl_xor_sync(0xffffffffu, lsum0, 1);
    lsum0 += __shfl_xor_sync(0xffffffffu, lsum0, 2);
    lsum1 += __shfl_xor_sync(0xffffffffu, lsum1, 1);
    lsum1 += __shfl_xor_sync(0xffffffffu, lsum1, 2);
    float inv0 = v0 ? (1.f / lsum0) : 0.f;
    float inv1 = v1 ? (1.f / lsum1) : 0.f;

    #pragma unroll
    for (int n = 0; n < 16; n++) {
        int c = n * 8 + (lane & 3) * 2;
        float2* p0 = (float2*)(og + (size_t)r0l * CDIM + c);
        float2* p1 = (float2*)(og + (size_t)(r0l + 8) * CDIM + c);
        *p0 = make_float2(oacc[n][0] * inv0, oacc[n][1] * inv0);
        *p1 = make_float2(oacc[n][2] * inv1, oacc[n][3] * inv1);
    }
}

// ============================================================================
extern "C" void kernel_launch(void* const* d_in, const int* in_sizes, int n_in,
                              void* d_out, int out_size)
{
    const float* x  = (const float*)d_in[0];
    const int*   vl = (const int*)  d_in[1];
    const float* qw = (const float*)d_in[2];
    const float* qb = (const float*)d_in[3];
    const float* kw = (const float*)d_in[4];
    const float* kb = (const float*)d_in[5];
    const float* vw = (const float*)d_in[6];
    const float* vb = (const float*)d_in[7];
    float* out = (float*)d_out;

    cudaFuncSetAttribute(qkv_kernel, cudaFuncAttributeMaxDynamicSharedMemorySize, QKV_SMEM);
    cudaFuncSetAttribute(attn_mma,   cudaFuncAttributeMaxDynamicSharedMemorySize, ATT_SMEM);

    qkv_kernel<<<(BATCH * SEQ) / 64, 256, QKV_SMEM>>>(x, vl, qw, qb, kw, kb, vw, vb);
    dim3 grid(SEQ / 128, BATCH);
    attn_mma<<<grid, 256, ATT_SMEM>>>(vl, out);
}

// round 5
// speedup vs baseline: 2.7018x; 1.3721x over previous
#include <cuda_runtime.h>
#include <cuda_bf16.h>
#include <math.h>
#include <stdint.h>

#define BATCH 64
#define SEQ   1024
#define CDIM  128
#define M0    40.0f

// bf16 hi/lo scratch (zero-initialized device globals):
// Q,K row-major [b*n][c]; V transposed [b][c][n]
__device__ __align__(16) unsigned short g_Qh[BATCH * SEQ * CDIM];
__device__ __align__(16) unsigned short g_Ql[BATCH * SEQ * CDIM];
__device__ __align__(16) unsigned short g_Kh[BATCH * SEQ * CDIM];
__device__ __align__(16) unsigned short g_Kl[BATCH * SEQ * CDIM];
__device__ __align__(16) unsigned short g_Vth[BATCH * CDIM * SEQ];
__device__ __align__(16) unsigned short g_Vtl[BATCH * CDIM * SEQ];

// ---------------- helpers ----------------
static __device__ __forceinline__ uint32_t smem_u32(const void* p) {
    uint32_t a;
    asm("{ .reg .u64 t; cvta.to.shared.u64 t, %1; cvt.u32.u64 %0, t; }" : "=r"(a) : "l"(p));
    return a;
}
static __device__ __forceinline__ void ldmx4(uint32_t a, uint32_t* r) {
    asm volatile("ldmatrix.sync.aligned.m8n8.x4.shared.b16 {%0,%1,%2,%3}, [%4];"
                 : "=r"(r[0]), "=r"(r[1]), "=r"(r[2]), "=r"(r[3]) : "r"(a));
}
static __device__ __forceinline__ void ldmx2(uint32_t a, uint32_t* r) {
    asm volatile("ldmatrix.sync.aligned.m8n8.x2.shared.b16 {%0,%1}, [%2];"
                 : "=r"(r[0]), "=r"(r[1]) : "r"(a));
}
static __device__ __forceinline__ void mma16816(float* d, const uint32_t* a, const uint32_t* b) {
    asm volatile("mma.sync.aligned.m16n8k16.row.col.f32.bf16.bf16.f32 "
                 "{%0,%1,%2,%3}, {%4,%5,%6,%7}, {%8,%9}, {%0,%1,%2,%3};"
                 : "+f"(d[0]), "+f"(d[1]), "+f"(d[2]), "+f"(d[3])
                 : "r"(a[0]), "r"(a[1]), "r"(a[2]), "r"(a[3]), "r"(b[0]), "r"(b[1]));
}
// pack two floats -> bf16x2 (first arg -> low half)
static __device__ __forceinline__ uint32_t cvt2(float lo, float hi) {
    uint32_t r;
    asm("cvt.rn.bf16x2.f32 %0, %1, %2;" : "=r"(r) : "f"(hi), "f"(lo));
    return r;
}
static __device__ __forceinline__ float lo_f(uint32_t h) { return __uint_as_float(h << 16); }
static __device__ __forceinline__ float hi_f(uint32_t h) { return __uint_as_float(h & 0xffff0000u); }
#define CP16(d, s) asm volatile("cp.async.cg.shared.global [%0], [%1], 16;" :: "r"(d), "l"(s))
#define CP_COMMIT() asm volatile("cp.async.commit_group;" ::: "memory")
#define CP_WAIT1()  asm volatile("cp.async.wait_group 1;" ::: "memory")

#define TS 272                    // stride: 256B-row tiles (Q/K/X/W)
#define VS 144                    // stride: 128B-row tiles (V^T stages)

// ---- attn smem layout (double-buffered 64-key stages) ----
#define A_QH   0
#define A_QL   34816
#define A_STG  69632
#define SSZ    71680              // per stage: KH 17408 | KL 17408 | VH 18432 | VL 18432
#define S_KH   0
#define S_KL   17408
#define S_VH   34816
#define S_VL   53248
#define ATT_SMEM (A_STG + 2 * SSZ)   // 212992

// ---- qkv smem layout ----
#define X_H    0
#define X_L    34816
#define W_H    69632
#define W_L    104448
#define QKV_SMEM 139264

// loaders (256 threads each)
static __device__ __forceinline__ void loadQ128(uint32_t sdst, const unsigned short* g, int tid) {
    #pragma unroll
    for (int i = 0; i < 8; i++) {
        int idx = tid + (i << 8);               // 2048 chunks
        int r = idx >> 4, c = idx & 15;
        CP16(sdst + (uint32_t)r * TS + (uint32_t)c * 16, (const void*)(g + (size_t)r * CDIM + (c << 3)));
    }
}
static __device__ __forceinline__ void loadK64(uint32_t sdst, const unsigned short* g, int tid) {
    #pragma unroll
    for (int i = 0; i < 4; i++) {
        int idx = tid + (i << 8);               // 1024 chunks
        int r = idx >> 4, c = idx & 15;
        CP16(sdst + (uint32_t)r * TS + (uint32_t)c * 16, (const void*)(g + (size_t)r * CDIM + (c << 3)));
    }
}
static __device__ __forceinline__ void loadV128x64(uint32_t sdst, const unsigned short* g, int tid) {
    #pragma unroll
    for (int i = 0; i < 4; i++) {
        int idx = tid + (i << 8);               // 1024 chunks
        int r = idx >> 3, c = idx & 7;
        CP16(sdst + (uint32_t)r * VS + (uint32_t)c * 16, (const void*)(g + (size_t)r * SEQ + (c << 3)));
    }
}

// ============================================================================
// Kernel 1: QKV projection via mma.sync, 3-term bf16 split.
// Block = 128 x-rows. V computed directly transposed (A=W, B=x).
// ============================================================================
__global__ __launch_bounds__(256)
void qkv_mma(const float* __restrict__ x, const int* __restrict__ vls,
             const float* __restrict__ qw, const float* __restrict__ qb,
             const float* __restrict__ kw, const float* __restrict__ kb,
             const float* __restrict__ vw, const float* __restrict__ vb)
{
    extern __shared__ __align__(16) char sm[];
    const uint32_t sb = smem_u32(sm);
    const int tid = threadIdx.x, wid = tid >> 5, lane = tid & 31;
    const int row0 = blockIdx.x * 128;
    const int b = row0 >> 10, n0 = row0 & 1023;
    if (n0 >= vls[b]) return;

    // convert x -> bf16 hi/lo smem tiles
    const float4* xg = (const float4*)(x + (size_t)row0 * CDIM);
    #pragma unroll
    for (int i = 0; i < 16; i++) {
        int idx = tid + (i << 8);
        int r = idx >> 5, c4 = idx & 31;
        float4 v = xg[r * 32 + c4];
        uint32_t h0 = cvt2(v.x, v.y), h1 = cvt2(v.z, v.w);
        uint32_t l0 = cvt2(v.x - lo_f(h0), v.y - hi_f(h0));
        uint32_t l1 = cvt2(v.z - lo_f(h1), v.w - hi_f(h1));
        uint32_t ad = (uint32_t)r * TS + (uint32_t)c4 * 8;
        *(uint2*)(sm + X_H + ad) = make_uint2(h0, h1);
        *(uint2*)(sm + X_L + ad) = make_uint2(l0, l1);
    }

    const uint32_t qrow = (uint32_t)(wid * 16 + (lane & 15)) * TS + ((lane >> 4) & 1) * 16;
    const uint32_t brow = (uint32_t)(lane & 7) * TS + ((lane >> 3) & 1) * 16;
    const int r0l = wid * 16 + (lane >> 2);

    for (int w = 0; w < 3; w++) {
        const float* W  = (w == 0) ? qw : (w == 1) ? kw : vw;
        const float* Bs = (w == 0) ? qb : (w == 1) ? kb : vb;
        __syncthreads();
        const float4* wg = (const float4*)W;
        #pragma unroll
        for (int i = 0; i < 16; i++) {
            int idx = tid + (i << 8);
            int r = idx >> 5, c4 = idx & 31;
            float4 v = wg[r * 32 + c4];
            uint32_t h0 = cvt2(v.x, v.y), h1 = cvt2(v.z, v.w);
            uint32_t l0 = cvt2(v.x - lo_f(h0), v.y - hi_f(h0));
            uint32_t l1 = cvt2(v.z - lo_f(h1), v.w - hi_f(h1));
            uint32_t ad = (uint32_t)r * TS + (uint32_t)c4 * 8;
            *(uint2*)(sm + W_H + ad) = make_uint2(h0, h1);
            *(uint2*)(sm + W_L + ad) = make_uint2(l0, l1);
        }
        __syncthreads();

        const uint32_t Ah = sb + ((w < 2) ? X_H : W_H), Al = sb + ((w < 2) ? X_L : W_L);
        const uint32_t Bh = sb + ((w < 2) ? W_H : X_H), Bl = sb + ((w < 2) ? W_L : X_L);

        float acc[16][4];
        #pragma unroll
        for (int n = 0; n < 16; n++)
            #pragma unroll
            for (int q = 0; q < 4; q++) acc[n][q] = 0.f;

        #pragma unroll
        for (int ks = 0; ks < 8; ks++) {
            uint32_t ah[4], al[4];
            ldmx4(Ah + qrow + ks * 32, ah);
            ldmx4(Al + qrow + ks * 32, al);
            #pragma unroll
            for (int n = 0; n < 16; n++) {
                uint32_t bh[2], bl[2];
                uint32_t off = brow + (uint32_t)n * (8 * TS) + ks * 32;
                ldmx2(Bh + off, bh);
                ldmx2(Bl + off, bl);
                mma16816(acc[n], ah, bh);
                mma16816(acc[n], al, bh);
                mma16816(acc[n], ah, bl);
            }
        }

        if (w < 2) {
            unsigned short* Oh = (w == 0) ? g_Qh : g_Kh;
            unsigned short* Ol = (w == 0) ? g_Ql : g_Kl;
            size_t rA = (size_t)(row0 + r0l) * CDIM;
            size_t rB = (size_t)(row0 + r0l + 8) * CDIM;
            #pragma unroll
            for (int n = 0; n < 16; n++) {
                int c = n * 8 + (lane & 3) * 2;
                float b0 = __ldg(Bs + c), b1 = __ldg(Bs + c + 1);
                float v00 = acc[n][0] + b0, v01 = acc[n][1] + b1;
                float v10 = acc[n][2] + b0, v11 = acc[n][3] + b1;
                uint32_t hA = cvt2(v00, v01), hB = cvt2(v10, v11);
                *(uint32_t*)(Oh + rA + c) = hA;
                *(uint32_t*)(Oh + rB + c) = hB;
                *(uint32_t*)(Ol + rA + c) = cvt2(v00 - lo_f(hA), v01 - hi_f(hA));
                *(uint32_t*)(Ol + rB + c) = cvt2(v10 - lo_f(hB), v11 - hi_f(hB));
            }
        } else {
            // rows = channels, cols = x-rows -> natural V^T write
            float bc0 = __ldg(Bs + r0l), bc1 = __ldg(Bs + r0l + 8);
            size_t rA = (size_t)b * CDIM * SEQ + (size_t)r0l * SEQ + n0;
            size_t rB = rA + (size_t)8 * SEQ;
            #pragma unroll
            for (int n = 0; n < 16; n++) {
                int c = n * 8 + (lane & 3) * 2;
                float v00 = acc[n][0] + bc0, v01 = acc[n][1] + bc0;
                float v10 = acc[n][2] + bc1, v11 = acc[n][3] + bc1;
                uint32_t hA = cvt2(v00, v01), hB = cvt2(v10, v11);
                *(uint32_t*)(g_Vth + rA + c) = hA;
                *(uint32_t*)(g_Vth + rB + c) = hB;
                *(uint32_t*)(g_Vtl + rA + c) = cvt2(v00 - lo_f(hA), v01 - hi_f(hA));
                *(uint32_t*)(g_Vtl + rB + c) = cvt2(v10 - lo_f(hB), v11 - hi_f(hB));
            }
        }
    }
}

// ============================================================================
// Kernel 2: pipelined mma.sync flash attention.
// 64-key double-buffered stages; fixed-M0 softmax; O in registers.
// ============================================================================
__global__ __launch_bounds__(256)
void attn_mma(const int* __restrict__ vls, float* __restrict__ out)
{
    extern __shared__ __align__(16) char sm[];
    const uint32_t sb = smem_u32(sm);
    const int tid = threadIdx.x, wid = tid >> 5, lane = tid & 31;
    const int b = blockIdx.y, row0 = blockIdx.x * 128;
    const int vl = vls[b];
    float* og = out + ((size_t)b * SEQ + row0) * CDIM;

    if (row0 >= vl) {
        float4 z = make_float4(0.f, 0.f, 0.f, 0.f);
        float4* o4 = (float4*)og;
        for (int i = tid; i < 128 * 32; i += 256) o4[i] = z;
        return;
    }

    const uint32_t qrow = (uint32_t)(wid * 16 + (lane & 15)) * TS + ((lane >> 4) & 1) * 16;
    const uint32_t browK = (uint32_t)(lane & 7) * TS + ((lane >> 3) & 1) * 16;
    const uint32_t browV = (uint32_t)(lane & 7) * VS + ((lane >> 3) & 1) * 16;
    const int r0l = wid * 16 + (lane >> 2);
    const bool v0 = row0 + r0l < vl, v1 = row0 + r0l + 8 < vl;

    const size_t kbase = (size_t)b * SEQ * CDIM;
    const size_t vbase = (size_t)b * CDIM * SEQ;
    const int nst = (vl + 63) >> 6;

    // prologue: Q + stage 0 -> group 0
    loadQ128(sb + A_QH, g_Qh + kbase + (size_t)row0 * CDIM, tid);
    loadQ128(sb + A_QL, g_Ql + kbase + (size_t)row0 * CDIM, tid);
    {
        uint32_t st = sb + A_STG;
        loadK64(st + S_KH, g_Kh + kbase, tid);
        loadK64(st + S_KL, g_Kl + kbase, tid);
        loadV128x64(st + S_VH, g_Vth + vbase, tid);
        loadV128x64(st + S_VL, g_Vtl + vbase, tid);
    }
    CP_COMMIT();

    float oacc[16][4];
    #pragma unroll
    for (int n = 0; n < 16; n++)
        #pragma unroll
        for (int q = 0; q < 4; q++) oacc[n][q] = 0.f;
    float lsum0 = 0.f, lsum1 = 0.f;

    for (int t = 0; t < nst; t++) {
        if (t + 1 < nst) {                          // prefetch next stage
            uint32_t st = sb + A_STG + ((t + 1) & 1) * SSZ;
            loadK64(st + S_KH, g_Kh + kbase + (size_t)(t + 1) * 64 * CDIM, tid);
            loadK64(st + S_KL, g_Kl + kbase + (size_t)(t + 1) * 64 * CDIM, tid);
            loadV128x64(st + S_VH, g_Vth + vbase + (size_t)(t + 1) * 64, tid);
            loadV128x64(st + S_VL, g_Vtl + vbase + (size_t)(t + 1) * 64, tid);
        }
        CP_COMMIT();
        CP_WAIT1();
        __syncthreads();

        const uint32_t st = sb + A_STG + (t & 1) * SSZ;

        // ---- S = Q K^T (64 keys, 3 split terms) ----
        float sacc[8][4];
        #pragma unroll
        for (int n = 0; n < 8; n++)
            #pragma unroll
            for (int q = 0; q < 4; q++) sacc[n][q] = 0.f;

        #pragma unroll
        for (int ks = 0; ks < 8; ks++) {
            uint32_t qh[4], ql[4];
            ldmx4(sb + A_QH + qrow + ks * 32, qh);
            ldmx4(sb + A_QL + qrow + ks * 32, ql);
            #pragma unroll
            for (int n = 0; n < 8; n++) {
                uint32_t bh[2], bl[2];
                uint32_t off = browK + (uint32_t)n * (8 * TS) + ks * 32;
                ldmx2(st + S_KH + off, bh);
                ldmx2(st + S_KL + off, bl);
                mma16816(sacc[n], qh, bh);
                mma16816(sacc[n], ql, bh);
                mma16816(sacc[n], qh, bl);
            }
        }

        // ---- softmax ----
        const int cb = t * 64;
        #pragma unroll
        for (int n = 0; n < 8; n++) {
            int c0 = cb + n * 8 + (lane & 3) * 2;
            float e0 = (v0 && c0 < vl)     ? __expf(fminf(fmaxf(sacc[n][0] - M0, -80.f), 80.f)) : 0.f;
            float e1 = (v0 && c0 + 1 < vl) ? __expf(fminf(fmaxf(sacc[n][1] - M0, -80.f), 80.f)) : 0.f;
            float e2 = (v1 && c0 < vl)     ? __expf(fminf(fmaxf(sacc[n][2] - M0, -80.f), 80.f)) : 0.f;
            float e3 = (v1 && c0 + 1 < vl) ? __expf(fminf(fmaxf(sacc[n][3] - M0, -80.f), 80.f)) : 0.f;
            lsum0 += e0 + e1;
            lsum1 += e2 + e3;
            sacc[n][0] = e0; sacc[n][1] = e1; sacc[n][2] = e2; sacc[n][3] = e3;
        }

        // ---- O += P V (3 split terms) ----
        #pragma unroll
        for (int ks = 0; ks < 4; ks++) {
            const float* t0 = sacc[2 * ks];
            const float* t1 = sacc[2 * ks + 1];
            uint32_t ph[4], pl[4];
            ph[0] = cvt2(t0[0], t0[1]);
            ph[1] = cvt2(t0[2], t0[3]);
            ph[2] = cvt2(t1[0], t1[1]);
            ph[3] = cvt2(t1[2], t1[3]);
            pl[0] = cvt2(t0[0] - lo_f(ph[0]), t0[1] - hi_f(ph[0]));
            pl[1] = cvt2(t0[2] - lo_f(ph[1]), t0[3] - hi_f(ph[1]));
            pl[2] = cvt2(t1[0] - lo_f(ph[2]), t1[1] - hi_f(ph[2]));
            pl[3] = cvt2(t1[2] - lo_f(ph[3]), t1[3] - hi_f(ph[3]));
            #pragma unroll
            for (int n = 0; n < 16; n++) {
                uint32_t bh[2], bl[2];
                uint32_t off = browV + (uint32_t)n * (8 * VS) + ks * 32;
                ldmx2(st + S_VH + off, bh);
                ldmx2(st + S_VL + off, bl);
                mma16816(oacc[n], ph, bh);
                mma16816(oacc[n], pl, bh);
                mma16816(oacc[n], ph, bl);
            }
        }
        __syncthreads();   // stage buffer free for prefetch t+2
    }

    // ---- epilogue ----
    lsum0 += __shfl_xor_sync(0xffffffffu, lsum0, 1);
    lsum0 += __shfl_xor_sync(0xffffffffu, lsum0, 2);
    lsum1 += __shfl_xor_sync(0xffffffffu, lsum1, 1);
    lsum1 += __shfl_xor_sync(0xffffffffu, lsum1, 2);
    float inv0 = v0 ? (1.f / lsum0) : 0.f;
    float inv1 = v1 ? (1.f / lsum1) : 0.f;

    #pragma unroll
    for (int n = 0; n < 16; n++) {
        int c = n * 8 + (lane & 3) * 2;
        float2* p0 = (float2*)(og + (size_t)r0l * CDIM + c);
        float2* p1 = (float2*)(og + (size_t)(r0l + 8) * CDIM + c);
        *p0 = make_float2(oacc[n][0] * inv0, oacc[n][1] * inv0);
        *p1 = make_float2(oacc[n][2] * inv1, oacc[n][3] * inv1);
    }
}

// ============================================================================
extern "C" void kernel_launch(void* const* d_in, const int* in_sizes, int n_in,
                              void* d_out, int out_size)
{
    const float* x  = (const float*)d_in[0];
    const int*   vl = (const int*)  d_in[1];
    const float* qw = (const float*)d_in[2];
    const float* qb = (const float*)d_in[3];
    const float* kw = (const float*)d_in[4];
    const float* kb = (const float*)d_in[5];
    const float* vw = (const float*)d_in[6];
    const float* vb = (const float*)d_in[7];
    float* out = (float*)d_out;

    cudaFuncSetAttribute(qkv_mma,  cudaFuncAttributeMaxDynamicSharedMemorySize, QKV_SMEM);
    cudaFuncSetAttribute(attn_mma, cudaFuncAttributeMaxDynamicSharedMemorySize, ATT_SMEM);

    qkv_mma<<<(BATCH * SEQ) / 128, 256, QKV_SMEM>>>(x, vl, qw, qb, kw, kb, vw, vb);
    dim3 grid(SEQ / 128, BATCH);
    attn_mma<<<grid, 256, ATT_SMEM>>>(vl, out);
}

// round 6
// speedup vs baseline: 3.1728x; 1.1743x over previous
#include <cuda_runtime.h>
#include <cuda_bf16.h>
#include <math.h>
#include <stdint.h>

#define BATCH 64
#define SEQ   1024
#define CDIM  128
#define M0    40.0f

// bf16 hi/lo scratch (zero-initialized device globals):
// Q,K row-major [b*n][c]; V transposed [b][c][n]
__device__ __align__(16) unsigned short g_Qh[BATCH * SEQ * CDIM];
__device__ __align__(16) unsigned short g_Ql[BATCH * SEQ * CDIM];
__device__ __align__(16) unsigned short g_Kh[BATCH * SEQ * CDIM];
__device__ __align__(16) unsigned short g_Kl[BATCH * SEQ * CDIM];
__device__ __align__(16) unsigned short g_Vth[BATCH * CDIM * SEQ];
__device__ __align__(16) unsigned short g_Vtl[BATCH * CDIM * SEQ];

// ---------------- helpers ----------------
static __device__ __forceinline__ uint32_t smem_u32(const void* p) {
    uint32_t a;
    asm("{ .reg .u64 t; cvta.to.shared.u64 t, %1; cvt.u32.u64 %0, t; }" : "=r"(a) : "l"(p));
    return a;
}
static __device__ __forceinline__ void ldmx4(uint32_t a, uint32_t* r) {
    asm volatile("ldmatrix.sync.aligned.m8n8.x4.shared.b16 {%0,%1,%2,%3}, [%4];"
                 : "=r"(r[0]), "=r"(r[1]), "=r"(r[2]), "=r"(r[3]) : "r"(a));
}
static __device__ __forceinline__ void mma16816(float* d, const uint32_t* a, const uint32_t* b) {
    asm volatile("mma.sync.aligned.m16n8k16.row.col.f32.bf16.bf16.f32 "
                 "{%0,%1,%2,%3}, {%4,%5,%6,%7}, {%8,%9}, {%0,%1,%2,%3};"
                 : "+f"(d[0]), "+f"(d[1]), "+f"(d[2]), "+f"(d[3])
                 : "r"(a[0]), "r"(a[1]), "r"(a[2]), "r"(a[3]), "r"(b[0]), "r"(b[1]));
}
// pack two floats -> bf16x2 (first arg -> low half)
static __device__ __forceinline__ uint32_t cvt2(float lo, float hi) {
    uint32_t r;
    asm("cvt.rn.bf16x2.f32 %0, %1, %2;" : "=r"(r) : "f"(hi), "f"(lo));
    return r;
}
static __device__ __forceinline__ float lo_f(uint32_t h) { return __uint_as_float(h << 16); }
static __device__ __forceinline__ float hi_f(uint32_t h) { return __uint_as_float(h & 0xffff0000u); }
#define CP16(d, s) asm volatile("cp.async.cg.shared.global [%0], [%1], 16;" :: "r"(d), "l"(s))
#define CP_COMMIT() asm volatile("cp.async.commit_group;" ::: "memory")

#define TS 272                    // stride: 256B-row tiles (Q/K/X/W)
#define VS 144                    // stride: 128B-row tiles (V^T stages)

// ---- attn smem: 3 rotating stage buffers (buf2 initially holds Q) ----
#define SSZ    71680              // stage: KH 17408 | KL 17408 | VH 18432 | VL 18432
#define S_KH   0
#define S_KL   17408
#define S_VH   34816
#define S_VL   53248
#define QH_OFF 0                  // inside buf2 during prologue
#define QL_OFF 34816
#define ATT_SMEM (3 * SSZ)        // 215040

// ---- qkv smem layout ----
#define X_H    0
#define X_L    34816
#define W_H    69632
#define W_L    104448
#define QKV_SMEM 139264

// loaders (256 threads each)
static __device__ __forceinline__ void loadQ128(uint32_t sdst, const unsigned short* g, int tid) {
    #pragma unroll
    for (int i = 0; i < 8; i++) {
        int idx = tid + (i << 8);
        int r = idx >> 4, c = idx & 15;
        CP16(sdst + (uint32_t)r * TS + (uint32_t)c * 16, (const void*)(g + (size_t)r * CDIM + (c << 3)));
    }
}
static __device__ __forceinline__ void loadK64(uint32_t sdst, const unsigned short* g, int tid) {
    #pragma unroll
    for (int i = 0; i < 4; i++) {
        int idx = tid + (i << 8);
        int r = idx >> 4, c = idx & 15;
        CP16(sdst + (uint32_t)r * TS + (uint32_t)c * 16, (const void*)(g + (size_t)r * CDIM + (c << 3)));
    }
}
static __device__ __forceinline__ void loadV128x64(uint32_t sdst, const unsigned short* g, int tid) {
    #pragma unroll
    for (int i = 0; i < 4; i++) {
        int idx = tid + (i << 8);
        int r = idx >> 3, c = idx & 7;
        CP16(sdst + (uint32_t)r * VS + (uint32_t)c * 16, (const void*)(g + (size_t)r * SEQ + (c << 3)));
    }
}
static __device__ __forceinline__ void stage_load(uint32_t buf, size_t kbase, size_t vbase,
                                                  int kt, int tid) {
    loadK64(buf + S_KH, g_Kh + kbase + (size_t)kt * 64 * CDIM, tid);
    loadK64(buf + S_KL, g_Kl + kbase + (size_t)kt * 64 * CDIM, tid);
    loadV128x64(buf + S_VH, g_Vth + vbase + (size_t)kt * 64, tid);
    loadV128x64(buf + S_VL, g_Vtl + vbase + (size_t)kt * 64, tid);
}

// ============================================================================
// Kernel 1: QKV projection via mma.sync, 3-term bf16 split.
// ============================================================================
__global__ __launch_bounds__(256)
void qkv_mma(const float* __restrict__ x, const int* __restrict__ vls,
             const float* __restrict__ qw, const float* __restrict__ qb,
             const float* __restrict__ kw, const float* __restrict__ kb,
             const float* __restrict__ vw, const float* __restrict__ vb)
{
    extern __shared__ __align__(16) char sm[];
    const uint32_t sb = smem_u32(sm);
    const int tid = threadIdx.x, wid = tid >> 5, lane = tid & 31;
    const int row0 = blockIdx.x * 128;
    const int b = row0 >> 10, n0 = row0 & 1023;
    if (n0 >= vls[b]) return;

    const float4* xg = (const float4*)(x + (size_t)row0 * CDIM);
    #pragma unroll
    for (int i = 0; i < 16; i++) {
        int idx = tid + (i << 8);
        int r = idx >> 5, c4 = idx & 31;
        float4 v = xg[r * 32 + c4];
        uint32_t h0 = cvt2(v.x, v.y), h1 = cvt2(v.z, v.w);
        uint32_t l0 = cvt2(v.x - lo_f(h0), v.y - hi_f(h0));
        uint32_t l1 = cvt2(v.z - lo_f(h1), v.w - hi_f(h1));
        uint32_t ad = (uint32_t)r * TS + (uint32_t)c4 * 8;
        *(uint2*)(sm + X_H + ad) = make_uint2(h0, h1);
        *(uint2*)(sm + X_L + ad) = make_uint2(l0, l1);
    }

    const uint32_t qrow = (uint32_t)(wid * 16 + (lane & 15)) * TS + ((lane >> 4) & 1) * 16;
    const uint32_t brow = (uint32_t)(lane & 7) * TS + ((lane >> 3) & 1) * 16;
    const int r0l = wid * 16 + (lane >> 2);

    for (int w = 0; w < 3; w++) {
        const float* W  = (w == 0) ? qw : (w == 1) ? kw : vw;
        const float* Bs = (w == 0) ? qb : (w == 1) ? kb : vb;
        __syncthreads();
        const float4* wg = (const float4*)W;
        #pragma unroll
        for (int i = 0; i < 16; i++) {
            int idx = tid + (i << 8);
            int r = idx >> 5, c4 = idx & 31;
            float4 v = wg[r * 32 + c4];
            uint32_t h0 = cvt2(v.x, v.y), h1 = cvt2(v.z, v.w);
            uint32_t l0 = cvt2(v.x - lo_f(h0), v.y - hi_f(h0));
            uint32_t l1 = cvt2(v.z - lo_f(h1), v.w - hi_f(h1));
            uint32_t ad = (uint32_t)r * TS + (uint32_t)c4 * 8;
            *(uint2*)(sm + W_H + ad) = make_uint2(h0, h1);
            *(uint2*)(sm + W_L + ad) = make_uint2(l0, l1);
        }
        __syncthreads();

        const uint32_t Ah = sb + ((w < 2) ? X_H : W_H), Al = sb + ((w < 2) ? X_L : W_L);
        const uint32_t Bh = sb + ((w < 2) ? W_H : X_H), Bl = sb + ((w < 2) ? W_L : X_L);

        float acc[16][4];
        #pragma unroll
        for (int n = 0; n < 16; n++)
            #pragma unroll
            for (int q = 0; q < 4; q++) acc[n][q] = 0.f;

        #pragma unroll
        for (int ks = 0; ks < 8; ks++) {
            uint32_t ah[4], al[4];
            ldmx4(Ah + qrow + ks * 32, ah);
            ldmx4(Al + qrow + ks * 32, al);
            #pragma unroll
            for (int n = 0; n < 16; n++) {
                uint32_t bh[2], bl[2];
                uint32_t off = brow + (uint32_t)n * (8 * TS) + ks * 32;
                asm volatile("ldmatrix.sync.aligned.m8n8.x2.shared.b16 {%0,%1}, [%2];"
                             : "=r"(bh[0]), "=r"(bh[1]) : "r"(Bh + off));
                asm volatile("ldmatrix.sync.aligned.m8n8.x2.shared.b16 {%0,%1}, [%2];"
                             : "=r"(bl[0]), "=r"(bl[1]) : "r"(Bl + off));
                mma16816(acc[n], ah, bh);
                mma16816(acc[n], al, bh);
                mma16816(acc[n], ah, bl);
            }
        }

        if (w < 2) {
            unsigned short* Oh = (w == 0) ? g_Qh : g_Kh;
            unsigned short* Ol = (w == 0) ? g_Ql : g_Kl;
            size_t rA = (size_t)(row0 + r0l) * CDIM;
            size_t rB = (size_t)(row0 + r0l + 8) * CDIM;
            #pragma unroll
            for (int n = 0; n < 16; n++) {
                int c = n * 8 + (lane & 3) * 2;
                float b0 = __ldg(Bs + c), b1 = __ldg(Bs + c + 1);
                float v00 = acc[n][0] + b0, v01 = acc[n][1] + b1;
                float v10 = acc[n][2] + b0, v11 = acc[n][3] + b1;
                uint32_t hA = cvt2(v00, v01), hB = cvt2(v10, v11);
                *(uint32_t*)(Oh + rA + c) = hA;
                *(uint32_t*)(Oh + rB + c) = hB;
                *(uint32_t*)(Ol + rA + c) = cvt2(v00 - lo_f(hA), v01 - hi_f(hA));
                *(uint32_t*)(Ol + rB + c) = cvt2(v10 - lo_f(hB), v11 - hi_f(hB));
            }
        } else {
            float bc0 = __ldg(Bs + r0l), bc1 = __ldg(Bs + r0l + 8);
            size_t rA = (size_t)b * CDIM * SEQ + (size_t)r0l * SEQ + n0;
            size_t rB = rA + (size_t)8 * SEQ;
            #pragma unroll
            for (int n = 0; n < 16; n++) {
                int c = n * 8 + (lane & 3) * 2;
                float v00 = acc[n][0] + bc0, v01 = acc[n][1] + bc0;
                float v10 = acc[n][2] + bc1, v11 = acc[n][3] + bc1;
                uint32_t hA = cvt2(v00, v01), hB = cvt2(v10, v11);
                *(uint32_t*)(g_Vth + rA + c) = hA;
                *(uint32_t*)(g_Vth + rB + c) = hB;
                *(uint32_t*)(g_Vtl + rA + c) = cvt2(v00 - lo_f(hA), v01 - hi_f(hA));
                *(uint32_t*)(g_Vtl + rB + c) = cvt2(v10 - lo_f(hB), v11 - hi_f(hB));
            }
        }
    }
}

// ============================================================================
// Kernel 2: pipelined flash attention. Q fragments hoisted to registers,
// triple-buffered 64-key stages (distance-2 prefetch), one bar/stage,
// ldmatrix x4 dual-n B-operands.
// ============================================================================
__global__ __launch_bounds__(256)
void attn_mma(const int* __restrict__ vls, float* __restrict__ out)
{
    extern __shared__ __align__(16) char sm[];
    const uint32_t sb = smem_u32(sm);
    const int tid = threadIdx.x, wid = tid >> 5, lane = tid & 31;
    const int b = blockIdx.y, row0 = blockIdx.x * 128;
    const int vl = vls[b];
    float* og = out + ((size_t)b * SEQ + row0) * CDIM;

    if (row0 >= vl) {
        float4 z = make_float4(0.f, 0.f, 0.f, 0.f);
        float4* o4 = (float4*)og;
        for (int i = tid; i < 128 * 32; i += 256) o4[i] = z;
        return;
    }

    const uint32_t qrow  = (uint32_t)(wid * 16 + (lane & 15)) * TS + ((lane >> 4) & 1) * 16;
    const uint32_t brwK = (uint32_t)((lane & 7) + ((lane >> 4) << 3)) * TS + ((lane >> 3) & 1) * 16;
    const uint32_t brwV = (uint32_t)((lane & 7) + ((lane >> 4) << 3)) * VS + ((lane >> 3) & 1) * 16;
    const int r0l = wid * 16 + (lane >> 2);
    const bool v0 = row0 + r0l < vl, v1 = row0 + r0l + 8 < vl;

    const size_t kbase = (size_t)b * SEQ * CDIM;
    const size_t vbase = (size_t)b * CDIM * SEQ;
    const int nst = (vl + 63) >> 6;
    const uint32_t buf0 = sb, buf1 = sb + SSZ, buf2 = sb + 2 * SSZ;

    // prologue: Q -> buf2 (G0), s0 -> buf0 (G1), s1 -> buf1 (G2)
    loadQ128(buf2 + QH_OFF, g_Qh + kbase + (size_t)row0 * CDIM, tid);
    loadQ128(buf2 + QL_OFF, g_Ql + kbase + (size_t)row0 * CDIM, tid);
    CP_COMMIT();
    stage_load(buf0, kbase, vbase, 0, tid);
    CP_COMMIT();
    if (nst > 1) stage_load(buf1, kbase, vbase, 1, tid);
    CP_COMMIT();
    asm volatile("cp.async.wait_group 2;" ::: "memory");   // Q complete
    __syncthreads();

    // hoist Q fragments (invariant across stages)
    uint32_t qh[8][4], ql[8][4];
    #pragma unroll
    for (int ks = 0; ks < 8; ks++) {
        ldmx4(buf2 + QH_OFF + qrow + ks * 32, qh[ks]);
        ldmx4(buf2 + QL_OFF + qrow + ks * 32, ql[ks]);
    }

    float oacc[16][4];
    #pragma unroll
    for (int n = 0; n < 16; n++)
        #pragma unroll
        for (int q = 0; q < 4; q++) oacc[n][q] = 0.f;
    float lsum0 = 0.f, lsum1 = 0.f;

    for (int t = 0; t < nst; t++) {
        asm volatile("cp.async.wait_group 1;" ::: "memory");   // stage t resident
        __syncthreads();                                        // all warps done with t-1
        if (t + 2 < nst) {
            uint32_t pb = (t + 2 == 2) ? buf2 : ((t + 2) % 3 == 0 ? buf0 : ((t + 2) % 3 == 1 ? buf1 : buf2));
            stage_load(pb, kbase, vbase, t + 2, tid);
        }
        CP_COMMIT();                                            // real or empty group

        const uint32_t st = (t % 3 == 0) ? buf0 : (t % 3 == 1) ? buf1 : buf2;

        // ---- S = Q K^T (3 split terms, dual-n x4 B loads) ----
        float sacc[8][4];
        #pragma unroll
        for (int n = 0; n < 8; n++)
            #pragma unroll
            for (int q = 0; q < 4; q++) sacc[n][q] = 0.f;

        #pragma unroll
        for (int ks = 0; ks < 8; ks++) {
            #pragma unroll
            for (int np = 0; np < 4; np++) {
                uint32_t bh[4], bl[4];
                uint32_t off = brwK + (uint32_t)np * (16 * TS) + ks * 32;
                ldmx4(st + S_KH + off, bh);
                ldmx4(st + S_KL + off, bl);
                mma16816(sacc[2 * np], qh[ks], bh);
                mma16816(sacc[2 * np], ql[ks], bh);
                mma16816(sacc[2 * np], qh[ks], bl);
                mma16816(sacc[2 * np + 1], qh[ks], bh + 2);
                mma16816(sacc[2 * np + 1], ql[ks], bh + 2);
                mma16816(sacc[2 * np + 1], qh[ks], bl + 2);
            }
        }

        // ---- softmax (fixed M0; masked lanes forced to 0, no clamps needed) ----
        const int cb = t * 64;
        #pragma unroll
        for (int n = 0; n < 8; n++) {
            int c0 = cb + n * 8 + (lane & 3) * 2;
            float e0 = (v0 && c0 < vl)     ? __expf(sacc[n][0] - M0) : 0.f;
            float e1 = (v0 && c0 + 1 < vl) ? __expf(sacc[n][1] - M0) : 0.f;
            float e2 = (v1 && c0 < vl)     ? __expf(sacc[n][2] - M0) : 0.f;
            float e3 = (v1 && c0 + 1 < vl) ? __expf(sacc[n][3] - M0) : 0.f;
            lsum0 += e0 + e1;
            lsum1 += e2 + e3;
            sacc[n][0] = e0; sacc[n][1] = e1; sacc[n][2] = e2; sacc[n][3] = e3;
        }

        // ---- O += P V (3 split terms, dual-n x4 B loads) ----
        #pragma unroll
        for (int ks = 0; ks < 4; ks++) {
            const float* t0 = sacc[2 * ks];
            const float* t1 = sacc[2 * ks + 1];
            uint32_t pfh[4], pfl[4];
            pfh[0] = cvt2(t0[0], t0[1]);
            pfh[1] = cvt2(t0[2], t0[3]);
            pfh[2] = cvt2(t1[0], t1[1]);
            pfh[3] = cvt2(t1[2], t1[3]);
            pfl[0] = cvt2(t0[0] - lo_f(pfh[0]), t0[1] - hi_f(pfh[0]));
            pfl[1] = cvt2(t0[2] - lo_f(pfh[1]), t0[3] - hi_f(pfh[1]));
            pfl[2] = cvt2(t1[0] - lo_f(pfh[2]), t1[1] - hi_f(pfh[2]));
            pfl[3] = cvt2(t1[2] - lo_f(pfh[3]), t1[3] - hi_f(pfh[3]));
            #pragma unroll
            for (int np = 0; np < 8; np++) {
                uint32_t bh[4], bl[4];
                uint32_t off = brwV + (uint32_t)np * (16 * VS) + ks * 32;
                ldmx4(st + S_VH + off, bh);
                ldmx4(st + S_VL + off, bl);
                mma16816(oacc[2 * np], pfh, bh);
                mma16816(oacc[2 * np], pfl, bh);
                mma16816(oacc[2 * np], pfh, bl);
                mma16816(oacc[2 * np + 1], pfh, bh + 2);
                mma16816(oacc[2 * np + 1], pfl, bh + 2);
                mma16816(oacc[2 * np + 1], pfh, bl + 2);
            }
        }
    }

    // ---- epilogue ----
    lsum0 += __shfl_xor_sync(0xffffffffu, lsum0, 1);
    lsum0 += __shfl_xor_sync(0xffffffffu, lsum0, 2);
    lsum1 += __shfl_xor_sync(0xffffffffu, lsum1, 1);
    lsum1 += __shfl_xor_sync(0xffffffffu, lsum1, 2);
    float inv0 = v0 ? (1.f / lsum0) : 0.f;
    float inv1 = v1 ? (1.f / lsum1) : 0.f;

    #pragma unroll
    for (int n = 0; n < 16; n++) {
        int c = n * 8 + (lane & 3) * 2;
        float2* p0 = (float2*)(og + (size_t)r0l * CDIM + c);
        float2* p1 = (float2*)(og + (size_t)(r0l + 8) * CDIM + c);
        *p0 = make_float2(oacc[n][0] * inv0, oacc[n][1] * inv0);
        *p1 = make_float2(oacc[n][2] * inv1, oacc[n][3] * inv1);
    }
}

// ============================================================================
extern "C" void kernel_launch(void* const* d_in, const int* in_sizes, int n_in,
                              void* d_out, int out_size)
{
    const float* x  = (const float*)d_in[0];
    const int*   vl = (const int*)  d_in[1];
    const float* qw = (const float*)d_in[2];
    const float* qb = (const float*)d_in[3];
    const float* kw = (const float*)d_in[4];
    const float* kb = (const float*)d_in[5];
    const float* vw = (const float*)d_in[6];
    const float* vb = (const float*)d_in[7];
    float* out = (float*)d_out;

    cudaFuncSetAttribute(qkv_mma,  cudaFuncAttributeMaxDynamicSharedMemorySize, QKV_SMEM);
    cudaFuncSetAttribute(attn_mma, cudaFuncAttributeMaxDynamicSharedMemorySize, ATT_SMEM);

    qkv_mma<<<(BATCH * SEQ) / 128, 256, QKV_SMEM>>>(x, vl, qw, qb, kw, kb, vw, vb);
    dim3 grid(SEQ / 128, BATCH);
    attn_mma<<<grid, 256, ATT_SMEM>>>(vl, out);
}